// round 10
// baseline (speedup 1.0000x reference)
#include <cuda_runtime.h>
#include <cuda_fp16.h>
#include <math.h>

#define HID   128
#define HEADS 4
#define HDIM  32
#define NMAX  50176
#define EMAX  800000

// ---------------- scratch ---------------------------------------------------
__device__ __half g_qh[NMAX * HID];
__device__ __half g_kh[NMAX * HID];
__device__ __half g_vh[NMAX * HID];
__device__ float  g_agg[NMAX * HID];     // unnormalized sum of w*v (fp32 atomics)
__device__ float  g_expsum[NMAX * HEADS];

// ---------------- mma helpers -----------------------------------------------
__device__ __forceinline__ unsigned smem_u32(const void* p) {
    return (unsigned)__cvta_generic_to_shared(p);
}
__device__ __forceinline__ void ldsm_x4(unsigned& r0, unsigned& r1,
                                        unsigned& r2, unsigned& r3, unsigned a) {
    asm volatile("ldmatrix.sync.aligned.m8n8.x4.shared.b16 {%0,%1,%2,%3},[%4];"
                 : "=r"(r0), "=r"(r1), "=r"(r2), "=r"(r3) : "r"(a));
}
__device__ __forceinline__ void mma16816(float* c, const unsigned* a, const unsigned* b) {
    asm volatile(
        "mma.sync.aligned.m16n8k16.row.col.f32.f16.f16.f32 "
        "{%0,%1,%2,%3},{%4,%5,%6,%7},{%8,%9},{%0,%1,%2,%3};"
        : "+f"(c[0]), "+f"(c[1]), "+f"(c[2]), "+f"(c[3])
        : "r"(a[0]), "r"(a[1]), "r"(a[2]), "r"(a[3]), "r"(b[0]), "r"(b[1]));
}

#define AKF 136   // full-K padded stride (halves): 128 + 8

// ---------------- zero scratch (vectorized) ----------------------------------
__global__ void zero_kernel(int n) {
    int i = blockIdx.x * blockDim.x + threadIdx.x;
    if (i < n * (HID / 4))
        *(float4*)&g_agg[i * 4] = make_float4(0.f, 0.f, 0.f, 0.f);
    if (i < n * HEADS) g_expsum[i] = 0.f;
}

// ---------------- QKV projections, full-K single-load (tensor cores) --------
// 128(M) x 128(N) per block, 8 warps x (32x64). blockIdx.y: 0=Q,1=K,2=V.
__global__ void __launch_bounds__(256, 2)
qkv_gemm(const float* __restrict__ h,
         const float* __restrict__ frac,
         const float* __restrict__ We,
         const float* __restrict__ be,
         const float* __restrict__ Wq, const float* __restrict__ bq,
         const float* __restrict__ Wk, const float* __restrict__ bk,
         const float* __restrict__ Wv, const float* __restrict__ bv,
         int n) {
    extern __shared__ __align__(16) char smem_raw[];
    __half (*As)[AKF] = (__half(*)[AKF])smem_raw;                       // 34816
    __half (*Bs)[AKF] = (__half(*)[AKF])(smem_raw + 128 * AKF * 2);    // 34816
    float (*Fr)[4]  = (float(*)[4])(smem_raw + 2 * 128 * AKF * 2);
    float (*Wes)[4] = Fr + 128;

    int m0 = blockIdx.x * 128;
    const float* W; const float* bias; __half* outbuf;
    if (blockIdx.y == 0)      { W = Wq; bias = bq; outbuf = g_qh; }
    else if (blockIdx.y == 1) { W = Wk; bias = bk; outbuf = g_kh; }
    else                      { W = Wv; bias = bv; outbuf = g_vh; }

    int tid = threadIdx.x;
    int wid = tid >> 5, lane = tid & 31;
    int wm = (wid & 3) * 32;
    int wn = (wid >> 2) * 64;

    if (tid < 128) {
        int kc = tid;
        Wes[kc][0] = We[kc * 3 + 0];
        Wes[kc][1] = We[kc * 3 + 1];
        Wes[kc][2] = We[kc * 3 + 2];
        Wes[kc][3] = be[kc];
        int m = m0 + tid;
        if (m < n) {
            Fr[tid][0] = frac[m * 3 + 0];
            Fr[tid][1] = frac[m * 3 + 1];
            Fr[tid][2] = frac[m * 3 + 2];
        } else {
            Fr[tid][0] = Fr[tid][1] = Fr[tid][2] = 0.f;
        }
    }
    __syncthreads();

    // full-K A tile (fused frac embedding)
    for (int idx = tid; idx < 128 * 32; idx += 256) {
        int r = idx >> 5;
        int k4 = (idx & 31) * 4;
        int m = m0 + r;
        float x[4] = {0.f, 0.f, 0.f, 0.f};
        if (m < n) {
            float4 hv = *(const float4*)&h[m * HID + k4];
            float f0 = Fr[r][0], f1 = Fr[r][1], f2 = Fr[r][2];
            x[0] = hv.x; x[1] = hv.y; x[2] = hv.z; x[3] = hv.w;
#pragma unroll
            for (int u = 0; u < 4; u++) {
                int kc = k4 + u;
                x[u] += f0 * Wes[kc][0] + f1 * Wes[kc][1] + f2 * Wes[kc][2] + Wes[kc][3];
            }
        }
        __half2* dst = (__half2*)&As[r][k4];
        dst[0] = __floats2half2_rn(x[0], x[1]);
        dst[1] = __floats2half2_rn(x[2], x[3]);
    }
    // full-K B tile
    for (int idx = tid; idx < 128 * 32; idx += 256) {
        int c = idx >> 5;
        int k4 = (idx & 31) * 4;
        float4 wv = *(const float4*)&W[c * HID + k4];
        __half2* dst = (__half2*)&Bs[c][k4];
        dst[0] = __floats2half2_rn(wv.x, wv.y);
        dst[1] = __floats2half2_rn(wv.z, wv.w);
    }
    __syncthreads();

    float acc[2][8][4];
#pragma unroll
    for (int i = 0; i < 2; i++)
#pragma unroll
        for (int j = 0; j < 8; j++)
#pragma unroll
            for (int t = 0; t < 4; t++) acc[i][j][t] = 0.f;

#pragma unroll
    for (int ks = 0; ks < 128; ks += 16) {
        unsigned af[2][4];
#pragma unroll
        for (int mf = 0; mf < 2; mf++) {
            unsigned a = smem_u32(&As[wm + mf * 16 + (lane & 15)][ks + (lane >> 4) * 8]);
            ldsm_x4(af[mf][0], af[mf][1], af[mf][2], af[mf][3], a);
        }
        unsigned bf[8][2];
#pragma unroll
        for (int ng = 0; ng < 4; ng++) {
            unsigned a = smem_u32(&Bs[wn + ng * 16 + (lane & 15)][ks + (lane >> 4) * 8]);
            unsigned r0, r1, r2, r3;
            ldsm_x4(r0, r1, r2, r3, a);
            bf[ng * 2][0] = r0; bf[ng * 2][1] = r2;
            bf[ng * 2 + 1][0] = r1; bf[ng * 2 + 1][1] = r3;
        }
#pragma unroll
        for (int mf = 0; mf < 2; mf++)
#pragma unroll
            for (int nf = 0; nf < 8; nf++)
                mma16816(acc[mf][nf], af[mf], bf[nf]);
    }

    // epilogue: add bias, store fp16
#pragma unroll
    for (int mf = 0; mf < 2; mf++) {
        int r0 = m0 + wm + mf * 16 + (lane >> 2);
#pragma unroll
        for (int nf = 0; nf < 8; nf++) {
            int c = wn + nf * 8 + (lane & 3) * 2;
            float b0 = bias[c], b1 = bias[c + 1];
            if (r0 < n)
                *(__half2*)&outbuf[r0 * HID + c] =
                    __floats2half2_rn(acc[mf][nf][0] + b0, acc[mf][nf][1] + b1);
            if (r0 + 8 < n)
                *(__half2*)&outbuf[(r0 + 8) * HID + c] =
                    __floats2half2_rn(acc[mf][nf][2] + b0, acc[mf][nf][3] + b1);
        }
    }
}

// ---------------- fused per-edge: FOUR edges per warp (8 lanes each) --------
// quarter = lane>>3 selects edge; sub = lane&7 covers 16 halves (32B).
// head = sub>>1 (2 lanes per head). Gate MLP: 4 hidden units per lane.
__global__ void edge_fused4(const int* __restrict__ ei,
                            const float* __restrict__ dist,
                            const float* __restrict__ Wg1, const float* __restrict__ bg1,
                            const float* __restrict__ Wg2, const float* __restrict__ bg2,
                            int E) {
    int warp = (blockIdx.x * blockDim.x + threadIdx.x) >> 5;
    int lane = threadIdx.x & 31;
    int e0 = warp * 4;
    if (e0 >= E) return;
    int quarter = lane >> 3;
    int sub     = lane & 7;
    int edge = e0 + quarter;
    bool valid = edge < E;
    int es = valid ? edge : e0;

    int row = __ldg(&ei[es]);
    int col = __ldg(&ei[E + es]);

    int boff = sub * 16;   // half index within row
    union H8 { float4 f; __half2 h[4]; } qa, qb, ka, kb, va, vb;
    qa.f = *(const float4*)&g_qh[row * HID + boff];
    qb.f = *(const float4*)&g_qh[row * HID + boff + 8];
    ka.f = *(const float4*)&g_kh[col * HID + boff];
    kb.f = *(const float4*)&g_kh[col * HID + boff + 8];
    va.f = *(const float4*)&g_vh[col * HID + boff];
    vb.f = *(const float4*)&g_vh[col * HID + boff + 8];

    float p = 0.f;
#pragma unroll
    for (int u = 0; u < 4; u++) {
        float2 qx = __half22float2(qa.h[u]), kx = __half22float2(ka.h[u]);
        float2 qy = __half22float2(qb.h[u]), ky = __half22float2(kb.h[u]);
        p += qx.x * kx.x + qx.y * kx.y + qy.x * ky.x + qy.y * ky.y;
    }
    // reduce over the 2 lanes of this head group
    p += __shfl_xor_sync(0xFFFFFFFFu, p, 1);

    // gate MLP: 1 -> 32 (silu) -> 1 (sigmoid); 4 hidden units per lane
    float d = __ldg(&dist[es]);
    int u0 = sub * 4;
    float4 w1 = *(const float4*)&Wg1[u0];
    float4 b1 = *(const float4*)&bg1[u0];
    float4 w2 = *(const float4*)&Wg2[u0];
    float t0 = fmaf(d, w1.x, b1.x);
    float t1 = fmaf(d, w1.y, b1.y);
    float t2 = fmaf(d, w1.z, b1.z);
    float t3 = fmaf(d, w1.w, b1.w);
    float gp = (t0 / (1.f + __expf(-t0))) * w2.x
             + (t1 / (1.f + __expf(-t1))) * w2.y
             + (t2 / (1.f + __expf(-t2))) * w2.z
             + (t3 / (1.f + __expf(-t3))) * w2.w;
    // reduce over the 8 lanes of this quarter
    gp += __shfl_xor_sync(0xFFFFFFFFu, gp, 4);
    gp += __shfl_xor_sync(0xFFFFFFFFu, gp, 2);
    gp += __shfl_xor_sync(0xFFFFFFFFu, gp, 1);
    float g = 1.f / (1.f + __expf(-(gp + bg2[0])));

    float w = __expf(p * 0.17677669529663687f * g);   // 1/sqrt(32)

    if (valid) {
        float* dst = &g_agg[row * HID + boff];
#pragma unroll
        for (int u = 0; u < 2; u++) {
            float2 x0 = __half22float2(va.h[u * 2]), x1 = __half22float2(va.h[u * 2 + 1]);
            asm volatile("red.global.add.v4.f32 [%0], {%1,%2,%3,%4};"
                         :: "l"(dst + u * 4), "f"(w * x0.x), "f"(w * x0.y),
                            "f"(w * x1.x), "f"(w * x1.y));
        }
#pragma unroll
        for (int u = 0; u < 2; u++) {
            float2 x0 = __half22float2(vb.h[u * 2]), x1 = __half22float2(vb.h[u * 2 + 1]);
            asm volatile("red.global.add.v4.f32 [%0], {%1,%2,%3,%4};"
                         :: "l"(dst + 8 + u * 4), "f"(w * x0.x), "f"(w * x0.y),
                            "f"(w * x1.x), "f"(w * x1.y));
        }
        if ((sub & 1) == 0)
            atomicAdd(&g_expsum[row * HEADS + (sub >> 1)], w);
    }
}

// ---------------- output projection, full-K (tensor cores) ------------------
__global__ void __launch_bounds__(256, 2)
out_gemm(const float* __restrict__ Wo,
         const float* __restrict__ bo,
         float* __restrict__ out, int n) {
    extern __shared__ __align__(16) char smem_raw[];
    __half (*As)[AKF] = (__half(*)[AKF])smem_raw;
    __half (*Bs)[AKF] = (__half(*)[AKF])(smem_raw + 128 * AKF * 2);
    float (*Inv)[4] = (float(*)[4])(smem_raw + 2 * 128 * AKF * 2);

    int m0 = blockIdx.x * 128;
    int tid = threadIdx.x;
    int wid = tid >> 5, lane = tid & 31;
    int wm = (wid & 3) * 32;
    int wn = (wid >> 2) * 64;

    for (int t = tid; t < 128 * HEADS; t += 256) {
        int ml = t >> 2, hd = t & 3;
        int m = m0 + ml;
        Inv[ml][hd] = (m < n) ? 1.f / (g_expsum[m * HEADS + hd] + 1e-16f) : 0.f;
    }
    __syncthreads();

    for (int idx = tid; idx < 128 * 32; idx += 256) {
        int r = idx >> 5;
        int k4 = (idx & 31) * 4;
        int m = m0 + r;
        float x[4] = {0.f, 0.f, 0.f, 0.f};
        if (m < n) {
            float4 av = *(const float4*)&g_agg[m * HID + k4];
            float iv = Inv[r][k4 >> 5];
            x[0] = av.x * iv; x[1] = av.y * iv; x[2] = av.z * iv; x[3] = av.w * iv;
        }
        __half2* dst = (__half2*)&As[r][k4];
        dst[0] = __floats2half2_rn(x[0], x[1]);
        dst[1] = __floats2half2_rn(x[2], x[3]);
    }
    for (int idx = tid; idx < 128 * 32; idx += 256) {
        int c = idx >> 5;
        int k4 = (idx & 31) * 4;
        float4 wv = *(const float4*)&Wo[c * HID + k4];
        __half2* dst = (__half2*)&Bs[c][k4];
        dst[0] = __floats2half2_rn(wv.x, wv.y);
        dst[1] = __floats2half2_rn(wv.z, wv.w);
    }
    __syncthreads();

    float acc[2][8][4];
#pragma unroll
    for (int i = 0; i < 2; i++)
#pragma unroll
        for (int j = 0; j < 8; j++)
#pragma unroll
            for (int t = 0; t < 4; t++) acc[i][j][t] = 0.f;

#pragma unroll
    for (int ks = 0; ks < 128; ks += 16) {
        unsigned af[2][4];
#pragma unroll
        for (int mf = 0; mf < 2; mf++) {
            unsigned a = smem_u32(&As[wm + mf * 16 + (lane & 15)][ks + (lane >> 4) * 8]);
            ldsm_x4(af[mf][0], af[mf][1], af[mf][2], af[mf][3], a);
        }
        unsigned bf[8][2];
#pragma unroll
        for (int ng = 0; ng < 4; ng++) {
            unsigned a = smem_u32(&Bs[wn + ng * 16 + (lane & 15)][ks + (lane >> 4) * 8]);
            unsigned r0, r1, r2, r3;
            ldsm_x4(r0, r1, r2, r3, a);
            bf[ng * 2][0] = r0; bf[ng * 2][1] = r2;
            bf[ng * 2 + 1][0] = r1; bf[ng * 2 + 1][1] = r3;
        }
#pragma unroll
        for (int mf = 0; mf < 2; mf++)
#pragma unroll
            for (int nf = 0; nf < 8; nf++)
                mma16816(acc[mf][nf], af[mf], bf[nf]);
    }

#pragma unroll
    for (int mf = 0; mf < 2; mf++) {
        int r0 = m0 + wm + mf * 16 + (lane >> 2);
#pragma unroll
        for (int nf = 0; nf < 8; nf++) {
            int c = wn + nf * 8 + (lane & 3) * 2;
            float b0 = bo[c], b1 = bo[c + 1];
            if (r0 < n)
                *(float2*)&out[r0 * HID + c] =
                    make_float2(acc[mf][nf][0] + b0, acc[mf][nf][1] + b1);
            if (r0 + 8 < n)
                *(float2*)&out[(r0 + 8) * HID + c] =
                    make_float2(acc[mf][nf][2] + b0, acc[mf][nf][3] + b1);
        }
    }
}

// ---------------- launch ----------------------------------------------------
extern "C" void kernel_launch(void* const* d_in, const int* in_sizes, int n_in,
                              void* d_out, int out_size) {
    const float* h    = (const float*)d_in[0];
    const float* frac = (const float*)d_in[1];
    const float* dist = (const float*)d_in[2];
    const int*   ei   = (const int*)d_in[3];
    const float* We   = (const float*)d_in[4];
    const float* be   = (const float*)d_in[5];
    const float* Wq   = (const float*)d_in[6];
    const float* bq   = (const float*)d_in[7];
    const float* Wk   = (const float*)d_in[8];
    const float* bk   = (const float*)d_in[9];
    const float* Wv   = (const float*)d_in[10];
    const float* bv   = (const float*)d_in[11];
    const float* Wo   = (const float*)d_in[12];
    const float* bo   = (const float*)d_in[13];
    const float* Wg1  = (const float*)d_in[14];
    const float* bg1  = (const float*)d_in[15];
    const float* Wg2  = (const float*)d_in[16];
    const float* bg2  = (const float*)d_in[17];

    int n = in_sizes[0] / HID;
    int E = in_sizes[2];
    float* out = (float*)d_out;

    int qkv_smem = 2 * 128 * AKF * 2 + 2 * 128 * 16;   // As+Bs + Fr+Wes
    int out_smem = 2 * 128 * AKF * 2 + 128 * 16;        // As+Bs + Inv
    static int smem_set = 0;
    if (!smem_set) {
        cudaFuncSetAttribute(qkv_gemm, cudaFuncAttributeMaxDynamicSharedMemorySize, qkv_smem);
        cudaFuncSetAttribute(out_gemm, cudaFuncAttributeMaxDynamicSharedMemorySize, out_smem);
        smem_set = 1;
    }

    zero_kernel<<<(n * (HID / 4) + 1023) / 1024, 1024>>>(n);

    dim3 gA((n + 127) / 128, 3);
    qkv_gemm<<<gA, 256, qkv_smem>>>(h, frac, We, be, Wq, bq, Wk, bk, Wv, bv, n);

    int warps = (E + 3) / 4;
    edge_fused4<<<(warps + 7) / 8, 256>>>(ei, dist, Wg1, bg1, Wg2, bg2, E);

    out_gemm<<<(n + 127) / 128, 256, out_smem>>>(Wo, bo, out, n);
}

// round 11
// speedup vs baseline: 1.1134x; 1.1134x over previous
#include <cuda_runtime.h>
#include <cuda_fp16.h>
#include <math.h>

#define HID   128
#define HEADS 4
#define HDIM  32
#define NMAX  50176
#define EMAX  800000

// ---------------- scratch ---------------------------------------------------
__device__ __half g_qh[NMAX * HID];
__device__ __half g_kh[NMAX * HID];
__device__ __half g_vh[NMAX * HID];
__device__ float  g_agg[NMAX * HID];     // unnormalized sum of w*v (fp32 atomics)
__device__ float  g_expsum[NMAX * HEADS];

// ---------------- mma helpers -----------------------------------------------
__device__ __forceinline__ unsigned smem_u32(const void* p) {
    return (unsigned)__cvta_generic_to_shared(p);
}
__device__ __forceinline__ void ldsm_x4(unsigned& r0, unsigned& r1,
                                        unsigned& r2, unsigned& r3, unsigned a) {
    asm volatile("ldmatrix.sync.aligned.m8n8.x4.shared.b16 {%0,%1,%2,%3},[%4];"
                 : "=r"(r0), "=r"(r1), "=r"(r2), "=r"(r3) : "r"(a));
}
__device__ __forceinline__ void mma16816(float* c, const unsigned* a, const unsigned* b) {
    asm volatile(
        "mma.sync.aligned.m16n8k16.row.col.f32.f16.f16.f32 "
        "{%0,%1,%2,%3},{%4,%5,%6,%7},{%8,%9},{%0,%1,%2,%3};"
        : "+f"(c[0]), "+f"(c[1]), "+f"(c[2]), "+f"(c[3])
        : "r"(a[0]), "r"(a[1]), "r"(a[2]), "r"(a[3]), "r"(b[0]), "r"(b[1]));
}

#define AK 72   // padded K stride (halves) for smem tiles

// ---------------- fused h_combined + QKV projections (tensor cores) ---------
// 128(M) x 128(N) per block, 8 warps x (32x64), K in 2 chunks of 64.
// blockIdx.y: 0=Q (also zeroes g_agg/g_expsum rows), 1=K, 2=V. Output fp16.
__global__ void __launch_bounds__(256, 2)
qkv_gemm(const float* __restrict__ h,
         const float* __restrict__ frac,
         const float* __restrict__ We,
         const float* __restrict__ be,
         const float* __restrict__ Wq, const float* __restrict__ bq,
         const float* __restrict__ Wk, const float* __restrict__ bk,
         const float* __restrict__ Wv, const float* __restrict__ bv,
         int n) {
    __shared__ __align__(16) __half As[128][AK];
    __shared__ __align__(16) __half Bs[128][AK];
    __shared__ float Wes[128][4];   // We0,We1,We2,be
    __shared__ float Fr[128][4];    // frac x,y,z

    int m0 = blockIdx.x * 128;
    const float* W; const float* bias; __half* outbuf;
    if (blockIdx.y == 0)      { W = Wq; bias = bq; outbuf = g_qh; }
    else if (blockIdx.y == 1) { W = Wk; bias = bk; outbuf = g_kh; }
    else                      { W = Wv; bias = bv; outbuf = g_vh; }

    int tid = threadIdx.x;
    int wid = tid >> 5, lane = tid & 31;
    int wm = (wid & 3) * 32;
    int wn = (wid >> 2) * 64;

    // Q-branch blocks zero the aggregation scratch for their rows
    if (blockIdx.y == 0) {
        int rows = min(128, n - m0);
        if (rows > 0) {
            for (int idx = tid; idx < rows * 32; idx += 256)
                *(float4*)&g_agg[m0 * HID + idx * 4] =
                    make_float4(0.f, 0.f, 0.f, 0.f);
            for (int idx = tid; idx < rows * HEADS; idx += 256)
                g_expsum[m0 * HEADS + idx] = 0.f;
        }
    }

    if (tid < 128) {
        int kc = tid;
        Wes[kc][0] = We[kc * 3 + 0];
        Wes[kc][1] = We[kc * 3 + 1];
        Wes[kc][2] = We[kc * 3 + 2];
        Wes[kc][3] = be[kc];
        int m = m0 + tid;
        if (m < n) {
            Fr[tid][0] = frac[m * 3 + 0];
            Fr[tid][1] = frac[m * 3 + 1];
            Fr[tid][2] = frac[m * 3 + 2];
        } else {
            Fr[tid][0] = Fr[tid][1] = Fr[tid][2] = 0.f;
        }
    }

    float acc[2][8][4];
#pragma unroll
    for (int i = 0; i < 2; i++)
#pragma unroll
        for (int j = 0; j < 8; j++)
#pragma unroll
            for (int t = 0; t < 4; t++) acc[i][j][t] = 0.f;

    __syncthreads();

    for (int k0 = 0; k0 < HID; k0 += 64) {
        // A tile: h_combined[m0..+127][k0..+63] -> fp16
        for (int idx = tid; idx < 128 * 16; idx += 256) {
            int r = idx >> 4;
            int k4 = (idx & 15) * 4;
            int m = m0 + r;
            float x[4] = {0.f, 0.f, 0.f, 0.f};
            if (m < n) {
                float4 hv = *(const float4*)&h[m * HID + k0 + k4];
                float f0 = Fr[r][0], f1 = Fr[r][1], f2 = Fr[r][2];
                x[0] = hv.x; x[1] = hv.y; x[2] = hv.z; x[3] = hv.w;
#pragma unroll
                for (int u = 0; u < 4; u++) {
                    int kc = k0 + k4 + u;
                    x[u] += f0 * Wes[kc][0] + f1 * Wes[kc][1] + f2 * Wes[kc][2] + Wes[kc][3];
                }
            }
            __half2* dst = (__half2*)&As[r][k4];
            dst[0] = __floats2half2_rn(x[0], x[1]);
            dst[1] = __floats2half2_rn(x[2], x[3]);
        }
        // B tile: W[c][k0..+63] -> fp16
        for (int idx = tid; idx < 128 * 16; idx += 256) {
            int c = idx >> 4;
            int k4 = (idx & 15) * 4;
            float4 wv = *(const float4*)&W[c * HID + k0 + k4];
            __half2* dst = (__half2*)&Bs[c][k4];
            dst[0] = __floats2half2_rn(wv.x, wv.y);
            dst[1] = __floats2half2_rn(wv.z, wv.w);
        }
        __syncthreads();

#pragma unroll
        for (int ks = 0; ks < 64; ks += 16) {
            unsigned af[2][4];
#pragma unroll
            for (int mf = 0; mf < 2; mf++) {
                unsigned a = smem_u32(&As[wm + mf * 16 + (lane & 15)][ks + (lane >> 4) * 8]);
                ldsm_x4(af[mf][0], af[mf][1], af[mf][2], af[mf][3], a);
            }
            unsigned bf[8][2];
#pragma unroll
            for (int ng = 0; ng < 4; ng++) {
                unsigned a = smem_u32(&Bs[wn + ng * 16 + (lane & 15)][ks + (lane >> 4) * 8]);
                unsigned r0, r1, r2, r3;
                ldsm_x4(r0, r1, r2, r3, a);
                bf[ng * 2][0] = r0; bf[ng * 2][1] = r2;
                bf[ng * 2 + 1][0] = r1; bf[ng * 2 + 1][1] = r3;
            }
#pragma unroll
            for (int mf = 0; mf < 2; mf++)
#pragma unroll
                for (int nf = 0; nf < 8; nf++)
                    mma16816(acc[mf][nf], af[mf], bf[nf]);
        }
        __syncthreads();
    }

    // epilogue: add bias, store fp16
#pragma unroll
    for (int mf = 0; mf < 2; mf++) {
        int r0 = m0 + wm + mf * 16 + (lane >> 2);
#pragma unroll
        for (int nf = 0; nf < 8; nf++) {
            int c = wn + nf * 8 + (lane & 3) * 2;
            float b0 = bias[c], b1 = bias[c + 1];
            if (r0 < n)
                *(__half2*)&outbuf[r0 * HID + c] =
                    __floats2half2_rn(acc[mf][nf][0] + b0, acc[mf][nf][1] + b1);
            if (r0 + 8 < n)
                *(__half2*)&outbuf[(r0 + 8) * HID + c] =
                    __floats2half2_rn(acc[mf][nf][2] + b0, acc[mf][nf][3] + b1);
        }
    }
}

// ---------------- fused per-edge: FOUR edges per warp (8 lanes each) --------
// quarter = lane>>3 selects edge; sub = lane&7 covers 32B of the row.
// head = sub>>1 (2 lanes per head). Gate MLP: 4 hidden units per lane.
__global__ void edge_fused4(const int* __restrict__ ei,
                            const float* __restrict__ dist,
                            const float* __restrict__ Wg1, const float* __restrict__ bg1,
                            const float* __restrict__ Wg2, const float* __restrict__ bg2,
                            int E) {
    int warp = (blockIdx.x * blockDim.x + threadIdx.x) >> 5;
    int lane = threadIdx.x & 31;
    int e0 = warp * 4;
    if (e0 >= E) return;
    int quarter = lane >> 3;
    int sub     = lane & 7;
    int edge = e0 + quarter;
    bool valid = edge < E;
    int es = valid ? edge : e0;

    int row = __ldg(&ei[es]);
    int col = __ldg(&ei[E + es]);

    int boff = sub * 16;   // half index within row
    union H8 { float4 f; __half2 h[4]; } qa, qb, ka, kb, va, vb;
    qa.f = *(const float4*)&g_qh[row * HID + boff];
    qb.f = *(const float4*)&g_qh[row * HID + boff + 8];
    ka.f = *(const float4*)&g_kh[col * HID + boff];
    kb.f = *(const float4*)&g_kh[col * HID + boff + 8];
    va.f = *(const float4*)&g_vh[col * HID + boff];
    vb.f = *(const float4*)&g_vh[col * HID + boff + 8];

    float p = 0.f;
#pragma unroll
    for (int u = 0; u < 4; u++) {
        float2 qx = __half22float2(qa.h[u]), kx = __half22float2(ka.h[u]);
        float2 qy = __half22float2(qb.h[u]), ky = __half22float2(kb.h[u]);
        p += qx.x * kx.x + qx.y * kx.y + qy.x * ky.x + qy.y * ky.y;
    }
    // reduce over the 2 lanes of this head group
    p += __shfl_xor_sync(0xFFFFFFFFu, p, 1);

    // gate MLP: 1 -> 32 (silu) -> 1 (sigmoid); 4 hidden units per lane
    float d = __ldg(&dist[es]);
    int u0 = sub * 4;
    float4 w1 = *(const float4*)&Wg1[u0];
    float4 b1 = *(const float4*)&bg1[u0];
    float4 w2 = *(const float4*)&Wg2[u0];
    float t0 = fmaf(d, w1.x, b1.x);
    float t1 = fmaf(d, w1.y, b1.y);
    float t2 = fmaf(d, w1.z, b1.z);
    float t3 = fmaf(d, w1.w, b1.w);
    float gp = (t0 / (1.f + __expf(-t0))) * w2.x
             + (t1 / (1.f + __expf(-t1))) * w2.y
             + (t2 / (1.f + __expf(-t2))) * w2.z
             + (t3 / (1.f + __expf(-t3))) * w2.w;
    // reduce over the 8 lanes of this quarter
    gp += __shfl_xor_sync(0xFFFFFFFFu, gp, 4);
    gp += __shfl_xor_sync(0xFFFFFFFFu, gp, 2);
    gp += __shfl_xor_sync(0xFFFFFFFFu, gp, 1);
    float g = 1.f / (1.f + __expf(-(gp + bg2[0])));

    float w = __expf(p * 0.17677669529663687f * g);   // 1/sqrt(32)

    if (valid) {
        float* dst = &g_agg[row * HID + boff];
#pragma unroll
        for (int u = 0; u < 2; u++) {
            float2 x0 = __half22float2(va.h[u * 2]), x1 = __half22float2(va.h[u * 2 + 1]);
            asm volatile("red.global.add.v4.f32 [%0], {%1,%2,%3,%4};"
                         :: "l"(dst + u * 4), "f"(w * x0.x), "f"(w * x0.y),
                            "f"(w * x1.x), "f"(w * x1.y));
        }
#pragma unroll
        for (int u = 0; u < 2; u++) {
            float2 x0 = __half22float2(vb.h[u * 2]), x1 = __half22float2(vb.h[u * 2 + 1]);
            asm volatile("red.global.add.v4.f32 [%0], {%1,%2,%3,%4};"
                         :: "l"(dst + 8 + u * 4), "f"(w * x0.x), "f"(w * x0.y),
                            "f"(w * x1.x), "f"(w * x1.y));
        }
        if ((sub & 1) == 0)
            atomicAdd(&g_expsum[row * HEADS + (sub >> 1)], w);
    }
}

// ---------------- output projection: (agg/expsum) @ Wo^T + bo (tensor) ------
__global__ void __launch_bounds__(256, 2)
out_gemm(const float* __restrict__ Wo,
         const float* __restrict__ bo,
         float* __restrict__ out, int n) {
    __shared__ __align__(16) __half As[128][AK];
    __shared__ __align__(16) __half Bs[128][AK];
    __shared__ float Inv[128][4];

    int m0 = blockIdx.x * 128;
    int tid = threadIdx.x;
    int wid = tid >> 5, lane = tid & 31;
    int wm = (wid & 3) * 32;
    int wn = (wid >> 2) * 64;

    for (int t = tid; t < 128 * HEADS; t += 256) {
        int ml = t >> 2, hd = t & 3;
        int m = m0 + ml;
        Inv[ml][hd] = (m < n) ? 1.f / (g_expsum[m * HEADS + hd] + 1e-16f) : 0.f;
    }

    float acc[2][8][4];
#pragma unroll
    for (int i = 0; i < 2; i++)
#pragma unroll
        for (int j = 0; j < 8; j++)
#pragma unroll
            for (int t = 0; t < 4; t++) acc[i][j][t] = 0.f;

    __syncthreads();

    for (int k0 = 0; k0 < HID; k0 += 64) {
        for (int idx = tid; idx < 128 * 16; idx += 256) {
            int r = idx >> 4;
            int k4 = (idx & 15) * 4;
            int m = m0 + r;
            float x[4] = {0.f, 0.f, 0.f, 0.f};
            if (m < n) {
                float4 av = *(const float4*)&g_agg[m * HID + k0 + k4];
                float iv = Inv[r][(k0 + k4) >> 5];
                x[0] = av.x * iv; x[1] = av.y * iv; x[2] = av.z * iv; x[3] = av.w * iv;
            }
            __half2* dst = (__half2*)&As[r][k4];
            dst[0] = __floats2half2_rn(x[0], x[1]);
            dst[1] = __floats2half2_rn(x[2], x[3]);
        }
        for (int idx = tid; idx < 128 * 16; idx += 256) {
            int c = idx >> 4;
            int k4 = (idx & 15) * 4;
            float4 wv = *(const float4*)&Wo[c * HID + k0 + k4];
            __half2* dst = (__half2*)&Bs[c][k4];
            dst[0] = __floats2half2_rn(wv.x, wv.y);
            dst[1] = __floats2half2_rn(wv.z, wv.w);
        }
        __syncthreads();

#pragma unroll
        for (int ks = 0; ks < 64; ks += 16) {
            unsigned af[2][4];
#pragma unroll
            for (int mf = 0; mf < 2; mf++) {
                unsigned a = smem_u32(&As[wm + mf * 16 + (lane & 15)][ks + (lane >> 4) * 8]);
                ldsm_x4(af[mf][0], af[mf][1], af[mf][2], af[mf][3], a);
            }
            unsigned bf[8][2];
#pragma unroll
            for (int ng = 0; ng < 4; ng++) {
                unsigned a = smem_u32(&Bs[wn + ng * 16 + (lane & 15)][ks + (lane >> 4) * 8]);
                unsigned r0, r1, r2, r3;
                ldsm_x4(r0, r1, r2, r3, a);
                bf[ng * 2][0] = r0; bf[ng * 2][1] = r2;
                bf[ng * 2 + 1][0] = r1; bf[ng * 2 + 1][1] = r3;
            }
#pragma unroll
            for (int mf = 0; mf < 2; mf++)
#pragma unroll
                for (int nf = 0; nf < 8; nf++)
                    mma16816(acc[mf][nf], af[mf], bf[nf]);
        }
        __syncthreads();
    }

#pragma unroll
    for (int mf = 0; mf < 2; mf++) {
        int r0 = m0 + wm + mf * 16 + (lane >> 2);
#pragma unroll
        for (int nf = 0; nf < 8; nf++) {
            int c = wn + nf * 8 + (lane & 3) * 2;
            float b0 = bo[c], b1 = bo[c + 1];
            if (r0 < n)
                *(float2*)&out[r0 * HID + c] =
                    make_float2(acc[mf][nf][0] + b0, acc[mf][nf][1] + b1);
            if (r0 + 8 < n)
                *(float2*)&out[(r0 + 8) * HID + c] =
                    make_float2(acc[mf][nf][2] + b0, acc[mf][nf][3] + b1);
        }
    }
}

// ---------------- launch ----------------------------------------------------
extern "C" void kernel_launch(void* const* d_in, const int* in_sizes, int n_in,
                              void* d_out, int out_size) {
    const float* h    = (const float*)d_in[0];
    const float* frac = (const float*)d_in[1];
    const float* dist = (const float*)d_in[2];
    const int*   ei   = (const int*)d_in[3];
    const float* We   = (const float*)d_in[4];
    const float* be   = (const float*)d_in[5];
    const float* Wq   = (const float*)d_in[6];
    const float* bq   = (const float*)d_in[7];
    const float* Wk   = (const float*)d_in[8];
    const float* bk   = (const float*)d_in[9];
    const float* Wv   = (const float*)d_in[10];
    const float* bv   = (const float*)d_in[11];
    const float* Wo   = (const float*)d_in[12];
    const float* bo   = (const float*)d_in[13];
    const float* Wg1  = (const float*)d_in[14];
    const float* bg1  = (const float*)d_in[15];
    const float* Wg2  = (const float*)d_in[16];
    const float* bg2  = (const float*)d_in[17];

    int n = in_sizes[0] / HID;
    int E = in_sizes[2];
    float* out = (float*)d_out;

    dim3 gA((n + 127) / 128, 3);
    qkv_gemm<<<gA, 256>>>(h, frac, We, be, Wq, bq, Wk, bk, Wv, bv, n);

    int warps = (E + 3) / 4;
    edge_fused4<<<(warps + 7) / 8, 256>>>(ei, dist, Wg1, bg1, Wg2, bg2, E);

    out_gemm<<<(n + 127) / 128, 256>>>(Wo, bo, out, n);
}

// round 12
// speedup vs baseline: 1.2565x; 1.1286x over previous
#include <cuda_runtime.h>
#include <cuda_fp16.h>
#include <math.h>

#define HID   128
#define HEADS 4
#define HDIM  32
#define NMAX  50176
#define EMAX  800000

// ---------------- scratch ---------------------------------------------------
__device__ __half g_hc[NMAX * HID];      // h_combined fp16
__device__ __half g_qh[NMAX * HID];
__device__ __half g_kh[NMAX * HID];
__device__ __half g_vh[NMAX * HID];
__device__ __half g_wqh[HID * HID];      // fp16 weights
__device__ __half g_wkh[HID * HID];
__device__ __half g_wvh[HID * HID];
__device__ __half g_woh[HID * HID];
__device__ float  g_agg[NMAX * HID];     // unnormalized sum of w*v (fp32 atomics)
__device__ float  g_expsum[NMAX * HEADS];

// ---------------- helpers ----------------------------------------------------
__device__ __forceinline__ unsigned smem_u32(const void* p) {
    return (unsigned)__cvta_generic_to_shared(p);
}
__device__ __forceinline__ void cp16(unsigned dst, const void* src) {
    asm volatile("cp.async.cg.shared.global [%0], [%1], 16;" :: "r"(dst), "l"(src));
}
__device__ __forceinline__ void cp_commit_wait() {
    asm volatile("cp.async.commit_group;");
    asm volatile("cp.async.wait_group 0;" ::: "memory");
}
__device__ __forceinline__ void ldsm_x4(unsigned& r0, unsigned& r1,
                                        unsigned& r2, unsigned& r3, unsigned a) {
    asm volatile("ldmatrix.sync.aligned.m8n8.x4.shared.b16 {%0,%1,%2,%3},[%4];"
                 : "=r"(r0), "=r"(r1), "=r"(r2), "=r"(r3) : "r"(a));
}
__device__ __forceinline__ void mma16816(float* c, const unsigned* a, const unsigned* b) {
    asm volatile(
        "mma.sync.aligned.m16n8k16.row.col.f32.f16.f16.f32 "
        "{%0,%1,%2,%3},{%4,%5,%6,%7},{%8,%9},{%0,%1,%2,%3};"
        : "+f"(c[0]), "+f"(c[1]), "+f"(c[2]), "+f"(c[3])
        : "r"(a[0]), "r"(a[1]), "r"(a[2]), "r"(a[3]), "r"(b[0]), "r"(b[1]));
}

#define AK 72   // padded K stride (halves) for smem tiles (144B rows, 16B aligned)

// ---------------- prep: convert weights to fp16 ------------------------------
__global__ void prep_weights(const float* __restrict__ Wq,
                             const float* __restrict__ Wk,
                             const float* __restrict__ Wv,
                             const float* __restrict__ Wo) {
    int i = blockIdx.x * blockDim.x + threadIdx.x;   // 4 elems per thread
    if (i >= 4 * HID * HID / 4) return;
    int which = i / (HID * HID / 4);
    int off = (i % (HID * HID / 4)) * 4;
    const float* src = (which == 0) ? Wq : (which == 1) ? Wk : (which == 2) ? Wv : Wo;
    __half* dst = (which == 0) ? g_wqh : (which == 1) ? g_wkh : (which == 2) ? g_wvh : g_woh;
    float4 v = *(const float4*)&src[off];
    __half2* d = (__half2*)&dst[off];
    d[0] = __floats2half2_rn(v.x, v.y);
    d[1] = __floats2half2_rn(v.z, v.w);
}

// ---------------- prep: h_combined -> fp16, zero agg/expsum ------------------
__global__ void prep_hc(const float* __restrict__ h,
                        const float* __restrict__ frac,
                        const float* __restrict__ We,
                        const float* __restrict__ be,
                        int n) {
    int idx = blockIdx.x * blockDim.x + threadIdx.x;   // one per 4 elems
    if (idx >= n * 32) return;
    int m = idx >> 5;
    int k4 = (idx & 31) * 4;
    float4 hv = *(const float4*)&h[m * HID + k4];
    float f0 = __ldg(&frac[m * 3 + 0]);
    float f1 = __ldg(&frac[m * 3 + 1]);
    float f2 = __ldg(&frac[m * 3 + 2]);
    float x[4] = {hv.x, hv.y, hv.z, hv.w};
#pragma unroll
    for (int u = 0; u < 4; u++) {
        int kc = k4 + u;
        x[u] += f0 * __ldg(&We[kc * 3 + 0]) + f1 * __ldg(&We[kc * 3 + 1])
              + f2 * __ldg(&We[kc * 3 + 2]) + __ldg(&be[kc]);
    }
    __half2* d = (__half2*)&g_hc[m * HID + k4];
    d[0] = __floats2half2_rn(x[0], x[1]);
    d[1] = __floats2half2_rn(x[2], x[3]);
    // zero aggregation scratch (same index space: n*32 x 4 floats = n*128)
    *(float4*)&g_agg[idx * 4] = make_float4(0.f, 0.f, 0.f, 0.f);
    if (idx < n * HEADS) g_expsum[idx] = 0.f;
}

// ---------------- QKV projections: pure fp16 GEMM w/ cp.async tiles ----------
// 128(M) x 128(N) per block, 8 warps x (32x64), K in 2 chunks of 64.
__global__ void __launch_bounds__(256, 2)
qkv_gemm(const float* __restrict__ bq,
         const float* __restrict__ bk,
         const float* __restrict__ bv,
         int n) {
    __shared__ __align__(16) __half As[128][AK];
    __shared__ __align__(16) __half Bs[128][AK];

    int m0 = blockIdx.x * 128;
    const __half* W; const float* bias; __half* outbuf;
    if (blockIdx.y == 0)      { W = g_wqh; bias = bq; outbuf = g_qh; }
    else if (blockIdx.y == 1) { W = g_wkh; bias = bk; outbuf = g_kh; }
    else                      { W = g_wvh; bias = bv; outbuf = g_vh; }

    int tid = threadIdx.x;
    int wid = tid >> 5, lane = tid & 31;
    int wm = (wid & 3) * 32;
    int wn = (wid >> 2) * 64;

    float acc[2][8][4];
#pragma unroll
    for (int i = 0; i < 2; i++)
#pragma unroll
        for (int j = 0; j < 8; j++)
#pragma unroll
            for (int t = 0; t < 4; t++) acc[i][j][t] = 0.f;

    for (int k0 = 0; k0 < HID; k0 += 64) {
        // A tile: g_hc[m0..+127][k0..+63]  (8x16B per row -> 1024 copies)
        for (int idx = tid; idx < 1024; idx += 256) {
            int r = idx >> 3;
            int c16 = idx & 7;
            cp16(smem_u32(&As[r][c16 * 8]), &g_hc[(m0 + r) * HID + k0 + c16 * 8]);
        }
        // B tile: W[c][k0..+63]
        for (int idx = tid; idx < 1024; idx += 256) {
            int c = idx >> 3;
            int c16 = idx & 7;
            cp16(smem_u32(&Bs[c][c16 * 8]), &W[c * HID + k0 + c16 * 8]);
        }
        cp_commit_wait();
        __syncthreads();

#pragma unroll
        for (int ks = 0; ks < 64; ks += 16) {
            unsigned af[2][4];
#pragma unroll
            for (int mf = 0; mf < 2; mf++) {
                unsigned a = smem_u32(&As[wm + mf * 16 + (lane & 15)][ks + (lane >> 4) * 8]);
                ldsm_x4(af[mf][0], af[mf][1], af[mf][2], af[mf][3], a);
            }
            unsigned bf[8][2];
#pragma unroll
            for (int ng = 0; ng < 4; ng++) {
                unsigned a = smem_u32(&Bs[wn + ng * 16 + (lane & 15)][ks + (lane >> 4) * 8]);
                unsigned r0, r1, r2, r3;
                ldsm_x4(r0, r1, r2, r3, a);
                bf[ng * 2][0] = r0; bf[ng * 2][1] = r2;
                bf[ng * 2 + 1][0] = r1; bf[ng * 2 + 1][1] = r3;
            }
#pragma unroll
            for (int mf = 0; mf < 2; mf++)
#pragma unroll
                for (int nf = 0; nf < 8; nf++)
                    mma16816(acc[mf][nf], af[mf], bf[nf]);
        }
        __syncthreads();
    }

    // epilogue: add bias, store fp16
#pragma unroll
    for (int mf = 0; mf < 2; mf++) {
        int r0 = m0 + wm + mf * 16 + (lane >> 2);
#pragma unroll
        for (int nf = 0; nf < 8; nf++) {
            int c = wn + nf * 8 + (lane & 3) * 2;
            float b0 = bias[c], b1 = bias[c + 1];
            if (r0 < n)
                *(__half2*)&outbuf[r0 * HID + c] =
                    __floats2half2_rn(acc[mf][nf][0] + b0, acc[mf][nf][1] + b1);
            if (r0 + 8 < n)
                *(__half2*)&outbuf[(r0 + 8) * HID + c] =
                    __floats2half2_rn(acc[mf][nf][2] + b0, acc[mf][nf][3] + b1);
        }
    }
}

// ---------------- fused per-edge: FOUR edges per warp (8 lanes each) --------
__global__ void edge_fused4(const int* __restrict__ ei,
                            const float* __restrict__ dist,
                            const float* __restrict__ Wg1, const float* __restrict__ bg1,
                            const float* __restrict__ Wg2, const float* __restrict__ bg2,
                            int E) {
    int warp = (blockIdx.x * blockDim.x + threadIdx.x) >> 5;
    int lane = threadIdx.x & 31;
    int e0 = warp * 4;
    if (e0 >= E) return;
    int quarter = lane >> 3;
    int sub     = lane & 7;
    int edge = e0 + quarter;
    bool valid = edge < E;
    int es = valid ? edge : e0;

    int row = __ldg(&ei[es]);
    int col = __ldg(&ei[E + es]);

    int boff = sub * 16;
    union H8 { float4 f; __half2 h[4]; } qa, qb, ka, kb, va, vb;
    qa.f = *(const float4*)&g_qh[row * HID + boff];
    qb.f = *(const float4*)&g_qh[row * HID + boff + 8];
    ka.f = *(const float4*)&g_kh[col * HID + boff];
    kb.f = *(const float4*)&g_kh[col * HID + boff + 8];
    va.f = *(const float4*)&g_vh[col * HID + boff];
    vb.f = *(const float4*)&g_vh[col * HID + boff + 8];

    float p = 0.f;
#pragma unroll
    for (int u = 0; u < 4; u++) {
        float2 qx = __half22float2(qa.h[u]), kx = __half22float2(ka.h[u]);
        float2 qy = __half22float2(qb.h[u]), ky = __half22float2(kb.h[u]);
        p += qx.x * kx.x + qx.y * kx.y + qy.x * ky.x + qy.y * ky.y;
    }
    p += __shfl_xor_sync(0xFFFFFFFFu, p, 1);

    float d = __ldg(&dist[es]);
    int u0 = sub * 4;
    float4 w1 = *(const float4*)&Wg1[u0];
    float4 b1 = *(const float4*)&bg1[u0];
    float4 w2 = *(const float4*)&Wg2[u0];
    float t0 = fmaf(d, w1.x, b1.x);
    float t1 = fmaf(d, w1.y, b1.y);
    float t2 = fmaf(d, w1.z, b1.z);
    float t3 = fmaf(d, w1.w, b1.w);
    float gp = (t0 / (1.f + __expf(-t0))) * w2.x
             + (t1 / (1.f + __expf(-t1))) * w2.y
             + (t2 / (1.f + __expf(-t2))) * w2.z
             + (t3 / (1.f + __expf(-t3))) * w2.w;
    gp += __shfl_xor_sync(0xFFFFFFFFu, gp, 4);
    gp += __shfl_xor_sync(0xFFFFFFFFu, gp, 2);
    gp += __shfl_xor_sync(0xFFFFFFFFu, gp, 1);
    float g = 1.f / (1.f + __expf(-(gp + bg2[0])));

    float w = __expf(p * 0.17677669529663687f * g);   // 1/sqrt(32)

    if (valid) {
        float* dst = &g_agg[row * HID + boff];
#pragma unroll
        for (int u = 0; u < 2; u++) {
            float2 x0 = __half22float2(va.h[u * 2]), x1 = __half22float2(va.h[u * 2 + 1]);
            asm volatile("red.global.add.v4.f32 [%0], {%1,%2,%3,%4};"
                         :: "l"(dst + u * 4), "f"(w * x0.x), "f"(w * x0.y),
                            "f"(w * x1.x), "f"(w * x1.y));
        }
#pragma unroll
        for (int u = 0; u < 2; u++) {
            float2 x0 = __half22float2(vb.h[u * 2]), x1 = __half22float2(vb.h[u * 2 + 1]);
            asm volatile("red.global.add.v4.f32 [%0], {%1,%2,%3,%4};"
                         :: "l"(dst + 8 + u * 4), "f"(w * x0.x), "f"(w * x0.y),
                            "f"(w * x1.x), "f"(w * x1.y));
        }
        if ((sub & 1) == 0)
            atomicAdd(&g_expsum[row * HEADS + (sub >> 1)], w);
    }
}

// ---------------- output projection: (agg/expsum) @ Wo^T + bo ---------------
__global__ void __launch_bounds__(256, 2)
out_gemm(const float* __restrict__ bo,
         float* __restrict__ out, int n) {
    __shared__ __align__(16) __half As[128][AK];
    __shared__ __align__(16) __half Bs[128][AK];
    __shared__ float Inv[128][4];

    int m0 = blockIdx.x * 128;
    int tid = threadIdx.x;
    int wid = tid >> 5, lane = tid & 31;
    int wm = (wid & 3) * 32;
    int wn = (wid >> 2) * 64;

    for (int t = tid; t < 128 * HEADS; t += 256) {
        int ml = t >> 2, hd = t & 3;
        int m = m0 + ml;
        Inv[ml][hd] = (m < n) ? 1.f / (g_expsum[m * HEADS + hd] + 1e-16f) : 0.f;
    }

    float acc[2][8][4];
#pragma unroll
    for (int i = 0; i < 2; i++)
#pragma unroll
        for (int j = 0; j < 8; j++)
#pragma unroll
            for (int t = 0; t < 4; t++) acc[i][j][t] = 0.f;

    __syncthreads();

    for (int k0 = 0; k0 < HID; k0 += 64) {
        // B tile via cp.async (fp16 preconverted Wo)
        for (int idx = tid; idx < 1024; idx += 256) {
            int c = idx >> 3;
            int c16 = idx & 7;
            cp16(smem_u32(&Bs[c][c16 * 8]), &g_woh[c * HID + k0 + c16 * 8]);
        }
        // A tile: normalize + convert (register staging)
        for (int idx = tid; idx < 128 * 16; idx += 256) {
            int r = idx >> 4;
            int k4 = (idx & 15) * 4;
            int m = m0 + r;
            float x[4] = {0.f, 0.f, 0.f, 0.f};
            if (m < n) {
                float4 av = *(const float4*)&g_agg[m * HID + k0 + k4];
                float iv = Inv[r][(k0 + k4) >> 5];
                x[0] = av.x * iv; x[1] = av.y * iv; x[2] = av.z * iv; x[3] = av.w * iv;
            }
            __half2* dst = (__half2*)&As[r][k4];
            dst[0] = __floats2half2_rn(x[0], x[1]);
            dst[1] = __floats2half2_rn(x[2], x[3]);
        }
        cp_commit_wait();
        __syncthreads();

#pragma unroll
        for (int ks = 0; ks < 64; ks += 16) {
            unsigned af[2][4];
#pragma unroll
            for (int mf = 0; mf < 2; mf++) {
                unsigned a = smem_u32(&As[wm + mf * 16 + (lane & 15)][ks + (lane >> 4) * 8]);
                ldsm_x4(af[mf][0], af[mf][1], af[mf][2], af[mf][3], a);
            }
            unsigned bf[8][2];
#pragma unroll
            for (int ng = 0; ng < 4; ng++) {
                unsigned a = smem_u32(&Bs[wn + ng * 16 + (lane & 15)][ks + (lane >> 4) * 8]);
                unsigned r0, r1, r2, r3;
                ldsm_x4(r0, r1, r2, r3, a);
                bf[ng * 2][0] = r0; bf[ng * 2][1] = r2;
                bf[ng * 2 + 1][0] = r1; bf[ng * 2 + 1][1] = r3;
            }
#pragma unroll
            for (int mf = 0; mf < 2; mf++)
#pragma unroll
                for (int nf = 0; nf < 8; nf++)
                    mma16816(acc[mf][nf], af[mf], bf[nf]);
        }
        __syncthreads();
    }

#pragma unroll
    for (int mf = 0; mf < 2; mf++) {
        int r0 = m0 + wm + mf * 16 + (lane >> 2);
#pragma unroll
        for (int nf = 0; nf < 8; nf++) {
            int c = wn + nf * 8 + (lane & 3) * 2;
            float b0 = bo[c], b1 = bo[c + 1];
            if (r0 < n)
                *(float2*)&out[r0 * HID + c] =
                    make_float2(acc[mf][nf][0] + b0, acc[mf][nf][1] + b1);
            if (r0 + 8 < n)
                *(float2*)&out[(r0 + 8) * HID + c] =
                    make_float2(acc[mf][nf][2] + b0, acc[mf][nf][3] + b1);
        }
    }
}

// ---------------- launch ----------------------------------------------------
extern "C" void kernel_launch(void* const* d_in, const int* in_sizes, int n_in,
                              void* d_out, int out_size) {
    const float* h    = (const float*)d_in[0];
    const float* frac = (const float*)d_in[1];
    const float* dist = (const float*)d_in[2];
    const int*   ei   = (const int*)d_in[3];
    const float* We   = (const float*)d_in[4];
    const float* be   = (const float*)d_in[5];
    const float* Wq   = (const float*)d_in[6];
    const float* bq   = (const float*)d_in[7];
    const float* Wk   = (const float*)d_in[8];
    const float* bk   = (const float*)d_in[9];
    const float* Wv   = (const float*)d_in[10];
    const float* bv   = (const float*)d_in[11];
    const float* Wo   = (const float*)d_in[12];
    const float* bo   = (const float*)d_in[13];
    const float* Wg1  = (const float*)d_in[14];
    const float* bg1  = (const float*)d_in[15];
    const float* Wg2  = (const float*)d_in[16];
    const float* bg2  = (const float*)d_in[17];

    int n = in_sizes[0] / HID;
    int E = in_sizes[2];
    float* out = (float*)d_out;

    prep_weights<<<(4 * HID * HID / 4 + 255) / 256, 256>>>(Wq, Wk, Wv, Wo);
    prep_hc<<<(n * 32 + 255) / 256, 256>>>(h, frac, We, be, n);

    dim3 gA((n + 127) / 128, 3);
    qkv_gemm<<<gA, 256>>>(bq, bk, bv, n);

    int warps = (E + 3) / 4;
    edge_fused4<<<(warps + 7) / 8, 256>>>(ei, dist, Wg1, bg1, Wg2, bg2, E);

    out_gemm<<<(n + 127) / 128, 256>>>(bo, out, n);
}

// round 13
// speedup vs baseline: 1.2596x; 1.0025x over previous
#include <cuda_runtime.h>
#include <cuda_fp16.h>
#include <math.h>

#define HID   128
#define HEADS 4
#define HDIM  32
#define NMAX  50176
#define EMAX  800000

// ---------------- scratch ---------------------------------------------------
__device__ __half g_hc[NMAX * HID];      // h_combined fp16
__device__ __half g_qh[NMAX * HID];
__device__ __half g_kh[NMAX * HID];
__device__ __half g_vh[NMAX * HID];
__device__ __half g_wqh[HID * HID];      // fp16 weights
__device__ __half g_wkh[HID * HID];
__device__ __half g_wvh[HID * HID];
__device__ __half g_woh[HID * HID];
__device__ float  g_agg[NMAX * HID];     // unnormalized sum of w*v (fp32 atomics)
__device__ float  g_expsum[NMAX * HEADS];

// ---------------- helpers ----------------------------------------------------
__device__ __forceinline__ unsigned smem_u32(const void* p) {
    return (unsigned)__cvta_generic_to_shared(p);
}
__device__ __forceinline__ void cp16(unsigned dst, const void* src) {
    asm volatile("cp.async.cg.shared.global [%0], [%1], 16;" :: "r"(dst), "l"(src));
}
__device__ __forceinline__ void cp_commit_wait() {
    asm volatile("cp.async.commit_group;");
    asm volatile("cp.async.wait_group 0;" ::: "memory");
}
__device__ __forceinline__ void ldsm_x4(unsigned& r0, unsigned& r1,
                                        unsigned& r2, unsigned& r3, unsigned a) {
    asm volatile("ldmatrix.sync.aligned.m8n8.x4.shared.b16 {%0,%1,%2,%3},[%4];"
                 : "=r"(r0), "=r"(r1), "=r"(r2), "=r"(r3) : "r"(a));
}
__device__ __forceinline__ void mma16816(float* c, const unsigned* a, const unsigned* b) {
    asm volatile(
        "mma.sync.aligned.m16n8k16.row.col.f32.f16.f16.f32 "
        "{%0,%1,%2,%3},{%4,%5,%6,%7},{%8,%9},{%0,%1,%2,%3};"
        : "+f"(c[0]), "+f"(c[1]), "+f"(c[2]), "+f"(c[3])
        : "r"(a[0]), "r"(a[1]), "r"(a[2]), "r"(a[3]), "r"(b[0]), "r"(b[1]));
}

#define AK 72   // padded K stride (halves) for smem tiles

// ---------------- prep: convert weights to fp16 ------------------------------
__global__ void prep_weights(const float* __restrict__ Wq,
                             const float* __restrict__ Wk,
                             const float* __restrict__ Wv,
                             const float* __restrict__ Wo) {
    int i = blockIdx.x * blockDim.x + threadIdx.x;   // 4 elems per thread
    if (i >= 4 * HID * HID / 4) return;
    int which = i / (HID * HID / 4);
    int off = (i % (HID * HID / 4)) * 4;
    const float* src = (which == 0) ? Wq : (which == 1) ? Wk : (which == 2) ? Wv : Wo;
    __half* dst = (which == 0) ? g_wqh : (which == 1) ? g_wkh : (which == 2) ? g_wvh : g_woh;
    float4 v = *(const float4*)&src[off];
    __half2* d = (__half2*)&dst[off];
    d[0] = __floats2half2_rn(v.x, v.y);
    d[1] = __floats2half2_rn(v.z, v.w);
}

// ---------------- prep: h_combined -> fp16, zero agg/expsum ------------------
__global__ void prep_hc(const float* __restrict__ h,
                        const float* __restrict__ frac,
                        const float* __restrict__ We,
                        const float* __restrict__ be,
                        int n) {
    int idx = blockIdx.x * blockDim.x + threadIdx.x;   // one per 4 elems
    if (idx >= n * 32) return;
    int m = idx >> 5;
    int k4 = (idx & 31) * 4;
    float4 hv = *(const float4*)&h[m * HID + k4];
    float f0 = __ldg(&frac[m * 3 + 0]);
    float f1 = __ldg(&frac[m * 3 + 1]);
    float f2 = __ldg(&frac[m * 3 + 2]);
    float x[4] = {hv.x, hv.y, hv.z, hv.w};
#pragma unroll
    for (int u = 0; u < 4; u++) {
        int kc = k4 + u;
        x[u] += f0 * __ldg(&We[kc * 3 + 0]) + f1 * __ldg(&We[kc * 3 + 1])
              + f2 * __ldg(&We[kc * 3 + 2]) + __ldg(&be[kc]);
    }
    __half2* d = (__half2*)&g_hc[m * HID + k4];
    d[0] = __floats2half2_rn(x[0], x[1]);
    d[1] = __floats2half2_rn(x[2], x[3]);
    *(float4*)&g_agg[idx * 4] = make_float4(0.f, 0.f, 0.f, 0.f);
    if (idx < n * HEADS) g_expsum[idx] = 0.f;
}

// ---------------- QKV projections: pure fp16 GEMM w/ cp.async tiles ----------
__global__ void __launch_bounds__(256, 2)
qkv_gemm(const float* __restrict__ bq,
         const float* __restrict__ bk,
         const float* __restrict__ bv,
         int n) {
    __shared__ __align__(16) __half As[128][AK];
    __shared__ __align__(16) __half Bs[128][AK];

    int m0 = blockIdx.x * 128;
    const __half* W; const float* bias; __half* outbuf;
    if (blockIdx.y == 0)      { W = g_wqh; bias = bq; outbuf = g_qh; }
    else if (blockIdx.y == 1) { W = g_wkh; bias = bk; outbuf = g_kh; }
    else                      { W = g_wvh; bias = bv; outbuf = g_vh; }

    int tid = threadIdx.x;
    int wid = tid >> 5, lane = tid & 31;
    int wm = (wid & 3) * 32;
    int wn = (wid >> 2) * 64;

    float acc[2][8][4];
#pragma unroll
    for (int i = 0; i < 2; i++)
#pragma unroll
        for (int j = 0; j < 8; j++)
#pragma unroll
            for (int t = 0; t < 4; t++) acc[i][j][t] = 0.f;

    for (int k0 = 0; k0 < HID; k0 += 64) {
        for (int idx = tid; idx < 1024; idx += 256) {
            int r = idx >> 3;
            int c16 = idx & 7;
            cp16(smem_u32(&As[r][c16 * 8]), &g_hc[(m0 + r) * HID + k0 + c16 * 8]);
        }
        for (int idx = tid; idx < 1024; idx += 256) {
            int c = idx >> 3;
            int c16 = idx & 7;
            cp16(smem_u32(&Bs[c][c16 * 8]), &W[c * HID + k0 + c16 * 8]);
        }
        cp_commit_wait();
        __syncthreads();

#pragma unroll
        for (int ks = 0; ks < 64; ks += 16) {
            unsigned af[2][4];
#pragma unroll
            for (int mf = 0; mf < 2; mf++) {
                unsigned a = smem_u32(&As[wm + mf * 16 + (lane & 15)][ks + (lane >> 4) * 8]);
                ldsm_x4(af[mf][0], af[mf][1], af[mf][2], af[mf][3], a);
            }
            unsigned bf[8][2];
#pragma unroll
            for (int ng = 0; ng < 4; ng++) {
                unsigned a = smem_u32(&Bs[wn + ng * 16 + (lane & 15)][ks + (lane >> 4) * 8]);
                unsigned r0, r1, r2, r3;
                ldsm_x4(r0, r1, r2, r3, a);
                bf[ng * 2][0] = r0; bf[ng * 2][1] = r2;
                bf[ng * 2 + 1][0] = r1; bf[ng * 2 + 1][1] = r3;
            }
#pragma unroll
            for (int mf = 0; mf < 2; mf++)
#pragma unroll
                for (int nf = 0; nf < 8; nf++)
                    mma16816(acc[mf][nf], af[mf], bf[nf]);
        }
        __syncthreads();
    }

#pragma unroll
    for (int mf = 0; mf < 2; mf++) {
        int r0 = m0 + wm + mf * 16 + (lane >> 2);
#pragma unroll
        for (int nf = 0; nf < 8; nf++) {
            int c = wn + nf * 8 + (lane & 3) * 2;
            float b0 = bias[c], b1 = bias[c + 1];
            if (r0 < n)
                *(__half2*)&outbuf[r0 * HID + c] =
                    __floats2half2_rn(acc[mf][nf][0] + b0, acc[mf][nf][1] + b1);
            if (r0 + 8 < n)
                *(__half2*)&outbuf[(r0 + 8) * HID + c] =
                    __floats2half2_rn(acc[mf][nf][2] + b0, acc[mf][nf][3] + b1);
        }
    }
}

// ---------------- fused per-edge: TWO edges per warp (16 lanes each) --------
// half = lane>>4 selects edge; sub = lane&15 covers 16B of the row.
// head = sub>>2 (4 lanes per head). Gate MLP: 2 hidden units per lane.
__global__ void edge_fused2(const int* __restrict__ ei,
                            const float* __restrict__ dist,
                            const float* __restrict__ Wg1, const float* __restrict__ bg1,
                            const float* __restrict__ Wg2, const float* __restrict__ bg2,
                            int E) {
    int warp = (blockIdx.x * blockDim.x + threadIdx.x) >> 5;
    int lane = threadIdx.x & 31;
    int e0 = warp * 2;
    if (e0 >= E) return;
    int half = lane >> 4;
    int sub  = lane & 15;
    int edge = e0 + half;
    bool valid = edge < E;
    int esafe = valid ? edge : e0;

    int row = __ldg(&ei[esafe]);
    int col = __ldg(&ei[E + esafe]);

    union { float4 f; __half2 h[4]; } q4, k4, v4;
    q4.f = *(const float4*)&g_qh[row * HID + sub * 8];
    k4.f = *(const float4*)&g_kh[col * HID + sub * 8];
    v4.f = *(const float4*)&g_vh[col * HID + sub * 8];

    float p = 0.f;
#pragma unroll
    for (int u = 0; u < 4; u++) {
        float2 qq = __half22float2(q4.h[u]);
        float2 kk = __half22float2(k4.h[u]);
        p += qq.x * kk.x + qq.y * kk.y;
    }
    // reduce over the 4 lanes of this head group
    p += __shfl_xor_sync(0xFFFFFFFFu, p, 1);
    p += __shfl_xor_sync(0xFFFFFFFFu, p, 2);

    // gate MLP: 1 -> 32 (silu) -> 1 (sigmoid); 2 hidden units per lane
    float d = __ldg(&dist[esafe]);
    int u0 = sub * 2;
    float t0 = fmaf(d, Wg1[u0], bg1[u0]);
    float t1 = fmaf(d, Wg1[u0 + 1], bg1[u0 + 1]);
    float gp = (t0 / (1.f + __expf(-t0))) * Wg2[u0]
             + (t1 / (1.f + __expf(-t1))) * Wg2[u0 + 1];
    gp += __shfl_xor_sync(0xFFFFFFFFu, gp, 8);
    gp += __shfl_xor_sync(0xFFFFFFFFu, gp, 4);
    gp += __shfl_xor_sync(0xFFFFFFFFu, gp, 2);
    gp += __shfl_xor_sync(0xFFFFFFFFu, gp, 1);
    float g = 1.f / (1.f + __expf(-(gp + bg2[0])));

    float w = __expf(p * 0.17677669529663687f * g);   // 1/sqrt(32)

    if (valid) {
        float* dst = &g_agg[row * HID + sub * 8];
        float2 v0 = __half22float2(v4.h[0]), v1 = __half22float2(v4.h[1]);
        float2 v2 = __half22float2(v4.h[2]), v3 = __half22float2(v4.h[3]);
        asm volatile("red.global.add.v4.f32 [%0], {%1,%2,%3,%4};"
                     :: "l"(dst), "f"(w * v0.x), "f"(w * v0.y),
                        "f"(w * v1.x), "f"(w * v1.y));
        asm volatile("red.global.add.v4.f32 [%0], {%1,%2,%3,%4};"
                     :: "l"(dst + 4), "f"(w * v2.x), "f"(w * v2.y),
                        "f"(w * v3.x), "f"(w * v3.y));
        if ((sub & 3) == 0)
            atomicAdd(&g_expsum[row * HEADS + (sub >> 2)], w);
    }
}

// ---------------- output projection: (agg/expsum) @ Wo^T + bo ---------------
__global__ void __launch_bounds__(256, 2)
out_gemm(const float* __restrict__ bo,
         float* __restrict__ out, int n) {
    __shared__ __align__(16) __half As[128][AK];
    __shared__ __align__(16) __half Bs[128][AK];
    __shared__ float Inv[128][4];

    int m0 = blockIdx.x * 128;
    int tid = threadIdx.x;
    int wid = tid >> 5, lane = tid & 31;
    int wm = (wid & 3) * 32;
    int wn = (wid >> 2) * 64;

    for (int t = tid; t < 128 * HEADS; t += 256) {
        int ml = t >> 2, hd = t & 3;
        int m = m0 + ml;
        Inv[ml][hd] = (m < n) ? 1.f / (g_expsum[m * HEADS + hd] + 1e-16f) : 0.f;
    }

    float acc[2][8][4];
#pragma unroll
    for (int i = 0; i < 2; i++)
#pragma unroll
        for (int j = 0; j < 8; j++)
#pragma unroll
            for (int t = 0; t < 4; t++) acc[i][j][t] = 0.f;

    __syncthreads();

    for (int k0 = 0; k0 < HID; k0 += 64) {
        for (int idx = tid; idx < 1024; idx += 256) {
            int c = idx >> 3;
            int c16 = idx & 7;
            cp16(smem_u32(&Bs[c][c16 * 8]), &g_woh[c * HID + k0 + c16 * 8]);
        }
        for (int idx = tid; idx < 128 * 16; idx += 256) {
            int r = idx >> 4;
            int k4 = (idx & 15) * 4;
            int m = m0 + r;
            float x[4] = {0.f, 0.f, 0.f, 0.f};
            if (m < n) {
                float4 av = *(const float4*)&g_agg[m * HID + k0 + k4];
                float iv = Inv[r][(k0 + k4) >> 5];
                x[0] = av.x * iv; x[1] = av.y * iv; x[2] = av.z * iv; x[3] = av.w * iv;
            }
            __half2* dst = (__half2*)&As[r][k4];
            dst[0] = __floats2half2_rn(x[0], x[1]);
            dst[1] = __floats2half2_rn(x[2], x[3]);
        }
        cp_commit_wait();
        __syncthreads();

#pragma unroll
        for (int ks = 0; ks < 64; ks += 16) {
            unsigned af[2][4];
#pragma unroll
            for (int mf = 0; mf < 2; mf++) {
                unsigned a = smem_u32(&As[wm + mf * 16 + (lane & 15)][ks + (lane >> 4) * 8]);
                ldsm_x4(af[mf][0], af[mf][1], af[mf][2], af[mf][3], a);
            }
            unsigned bf[8][2];
#pragma unroll
            for (int ng = 0; ng < 4; ng++) {
                unsigned a = smem_u32(&Bs[wn + ng * 16 + (lane & 15)][ks + (lane >> 4) * 8]);
                unsigned r0, r1, r2, r3;
                ldsm_x4(r0, r1, r2, r3, a);
                bf[ng * 2][0] = r0; bf[ng * 2][1] = r2;
                bf[ng * 2 + 1][0] = r1; bf[ng * 2 + 1][1] = r3;
            }
#pragma unroll
            for (int mf = 0; mf < 2; mf++)
#pragma unroll
                for (int nf = 0; nf < 8; nf++)
                    mma16816(acc[mf][nf], af[mf], bf[nf]);
        }
        __syncthreads();
    }

#pragma unroll
    for (int mf = 0; mf < 2; mf++) {
        int r0 = m0 + wm + mf * 16 + (lane >> 2);
#pragma unroll
        for (int nf = 0; nf < 8; nf++) {
            int c = wn + nf * 8 + (lane & 3) * 2;
            float b0 = bo[c], b1 = bo[c + 1];
            if (r0 < n)
                *(float2*)&out[r0 * HID + c] =
                    make_float2(acc[mf][nf][0] + b0, acc[mf][nf][1] + b1);
            if (r0 + 8 < n)
                *(float2*)&out[(r0 + 8) * HID + c] =
                    make_float2(acc[mf][nf][2] + b0, acc[mf][nf][3] + b1);
        }
    }
}

// ---------------- launch ----------------------------------------------------
extern "C" void kernel_launch(void* const* d_in, const int* in_sizes, int n_in,
                              void* d_out, int out_size) {
    const float* h    = (const float*)d_in[0];
    const float* frac = (const float*)d_in[1];
    const float* dist = (const float*)d_in[2];
    const int*   ei   = (const int*)d_in[3];
    const float* We   = (const float*)d_in[4];
    const float* be   = (const float*)d_in[5];
    const float* Wq   = (const float*)d_in[6];
    const float* bq   = (const float*)d_in[7];
    const float* Wk   = (const float*)d_in[8];
    const float* bk   = (const float*)d_in[9];
    const float* Wv   = (const float*)d_in[10];
    const float* bv   = (const float*)d_in[11];
    const float* Wo   = (const float*)d_in[12];
    const float* bo   = (const float*)d_in[13];
    const float* Wg1  = (const float*)d_in[14];
    const float* bg1  = (const float*)d_in[15];
    const float* Wg2  = (const float*)d_in[16];
    const float* bg2  = (const float*)d_in[17];

    int n = in_sizes[0] / HID;
    int E = in_sizes[2];
    float* out = (float*)d_out;

    prep_weights<<<(4 * HID * HID / 4 + 255) / 256, 256>>>(Wq, Wk, Wv, Wo);
    prep_hc<<<(n * 32 + 255) / 256, 256>>>(h, frac, We, be, n);

    dim3 gA((n + 127) / 128, 3);
    qkv_gemm<<<gA, 256>>>(bq, bk, bv, n);

    int warps = (E + 1) / 2;
    edge_fused2<<<(warps + 7) / 8, 256>>>(ei, dist, Wg1, bg1, Wg2, bg2, E);

    out_gemm<<<(n + 127) / 128, 256>>>(bo, out, n);
}